// round 15
// baseline (speedup 1.0000x reference)
#include <cuda_runtime.h>
#include <cuda_bf16.h>
#include <cuda_fp16.h>
#include <cstdint>

#define NROWS   32768
#define KCODES  2048
#define CDIM    256
#define ZQN     8388608
#define LOSS_OFF 8388608
#define IDX_OFF  8388609
#define NPART   2048
#define FILT_EPS 7.5e-4f

// B tile row stride in bf16 (256 data + 8 pad; 528B = 33*16; conflict-free frags)
#define RS 264

// ---- scratch (device globals; no allocation allowed) ----------------------
__device__ float          g_se[KCODES];
__device__ float          g_sz[NROWS];
__device__ float          g_min[NROWS];               // per-row fp32 min of tt
__device__ int            g_idx[NROWS];
__device__ double         g_part[NPART];
__device__ __nv_bfloat16  g_embh[KCODES * RS];         // emb in bf16, padded rows
__device__ __half         g_tth[(size_t)NROWS * KCODES]; // fp16 score dump (128MB)

// ---- helpers ---------------------------------------------------------------
__device__ __forceinline__ uint32_t smem_u32(const void* p) {
    uint32_t a;
    asm("{ .reg .u64 t; cvta.to.shared.u64 t, %1; cvt.u32.u64 %0, t; }"
        : "=r"(a) : "l"(p));
    return a;
}
__device__ __forceinline__ void cp16(uint32_t dst, const void* src) {
    asm volatile("cp.async.cg.shared.global [%0], [%1], 16;"
                 :: "r"(dst), "l"(src) : "memory");
}
#define CP_COMMIT() asm volatile("cp.async.commit_group;" ::: "memory")
#define CP_WAIT1()  asm volatile("cp.async.wait_group 1;" ::: "memory")
#define CP_WAIT0()  asm volatile("cp.async.wait_group 0;" ::: "memory")

// bf16 warp MMA m16n8k16 (Ampere-era PTX; valid on plain sm_103 target)
__device__ __forceinline__ void mma16816(float* d, const uint32_t* a, const uint32_t* b) {
    asm volatile(
        "mma.sync.aligned.m16n8k16.row.col.f32.bf16.bf16.f32 "
        "{%0,%1,%2,%3}, {%4,%5,%6,%7}, {%8,%9}, {%0,%1,%2,%3};"
        : "+f"(d[0]), "+f"(d[1]), "+f"(d[2]), "+f"(d[3])
        : "r"(a[0]), "r"(a[1]), "r"(a[2]), "r"(a[3]), "r"(b[0]), "r"(b[1]));
}
__device__ __forceinline__ void ldm4(uint32_t* r, uint32_t a) {
    asm volatile("ldmatrix.sync.aligned.m8n8.x4.shared.b16 {%0,%1,%2,%3}, [%4];"
        : "=r"(r[0]), "=r"(r[1]), "=r"(r[2]), "=r"(r[3]) : "r"(a));
}

// ---- smem layout for k_filter (bytes) --------------------------------------
#define SA    0                 // A: 128 x RS bf16                    67584
#define SB    67584             // B: 2 x (128 x RS) bf16             135168
#define SSE   202752            // se staging [2][128] f32              1024
#define SRM   203776            // rowmin [128][4] f32                  2048
#define SMEM_F 205824
#define BUFE  (128 * RS)

// ===========================================================================
// per-code / per-row squared norms (exact fp32, same sequences as R1)
// ===========================================================================
__global__ void k_se(const float* __restrict__ emb) {
    int k = blockIdx.x * 128 + threadIdx.x;
    const float4* e = (const float4*)(emb + (size_t)k * CDIM);
    float s = 0.f;
#pragma unroll 8
    for (int i = 0; i < CDIM / 4; i++) {
        float4 v = e[i];
        s += v.x * v.x; s += v.y * v.y; s += v.z * v.z; s += v.w * v.w;
    }
    g_se[k] = s;
}

__global__ void k_sz(const float* __restrict__ z) {
    int n = blockIdx.x * 256 + threadIdx.x;
    int b = n >> 12, s = n & 4095;
    const float* p = z + (size_t)b * 1048576 + s;
    float acc = 0.f;
#pragma unroll 8
    for (int c = 0; c < CDIM; c++) {
        float v = p[(size_t)c * 4096];
        acc += v * v;
    }
    g_sz[n] = acc;
}

// emb fp32 -> bf16 into padded [code][RS] layout
__global__ void k_cvt(const float* __restrict__ emb) {
    int g = blockIdx.x * 256 + threadIdx.x;
    int code = g >> 4, m = g & 15;
    const float4* src = (const float4*)(emb + (size_t)code * CDIM + m * 16);
    __nv_bfloat162 v[8];
#pragma unroll
    for (int i = 0; i < 4; i++) {
        float4 f = src[i];
        v[2 * i]     = __floats2bfloat162_rn(f.x, f.y);
        v[2 * i + 1] = __floats2bfloat162_rn(f.z, f.w);
    }
    __nv_bfloat162* dst = (__nv_bfloat162*)(g_embh + (size_t)code * RS + m * 16);
#pragma unroll
    for (int i = 0; i < 8; i++) dst[i] = v[i];
}

// ===========================================================================
// Warp-MMA bf16 score kernel, 512 threads, 4x4 warp grid (warp tile 32x32).
// Dumps tt = se - 2*dot as fp16 AND the per-row fp32 min (g_min).
// No emission, no counts, no atomics.
// ===========================================================================
__global__ __launch_bounds__(512, 1) void k_filter(const float* __restrict__ z) {
    extern __shared__ char smem[];
    __nv_bfloat16* As   = (__nv_bfloat16*)(smem + SA);
    float*         se_s = (float*)(smem + SSE);
    float*         rowm = (float*)(smem + SRM);
    const uint32_t sbase = smem_u32(smem);

    const int tid = threadIdx.x, lane = tid & 31, wid = tid >> 5;
    const int qr = lane >> 2, qc = lane & 3;
    const int WM = wid & 3, WN = wid >> 2;          // 4 x 4 warp grid
    const int n0 = blockIdx.x * 128;

    // ---- A fill: z rows n0..n0+127 -> bf16 As[row][c]
    {
        const float* zb = z + ((size_t)(n0 >> 12)) * 1048576 + (n0 & 4095);
#pragma unroll 8
        for (int i = 0; i < 64; i++) {
            int u = tid + i * 512;
            int row = u & 127, c = u >> 7;
            As[row * RS + c] = __float2bfloat16(zb[(size_t)c * 4096 + row]);
        }
    }
    rowm[tid] = 1e30f;                               // 512 slots = [128][4]

    // ---- ldmatrix per-lane base addresses ----
    const int l7 = lane & 7;
    const int a_row  = 32 * WM + l7 + 8 * ((lane >> 3) & 1);
    const int a_koff = (lane >> 4) * 8;
    const uint32_t a_base = sbase + SA + (uint32_t)((a_row * RS + a_koff) * 2);
    const int bt = lane >> 3;
    const int b_rowoff = 8 * (bt >> 1) + l7;
    const int b_koff = 8 * (bt & 1);
    const uint32_t b_lane_off = (uint32_t)(((32 * WN + b_rowoff) * RS + b_koff) * 2);

    // ---- B tile async loader ----
    auto issueB = [&](int t) {
        const __nv_bfloat16* src = g_embh + (size_t)t * 128 * RS;
        uint32_t dbase = sbase + SB + (t & 1) * (BUFE * 2);
#pragma unroll
        for (int i = 0; i < 8; i++) {
            int u = tid + i * 512;
            int n = u >> 5, m = u & 31;
            cp16(dbase + (uint32_t)(n * RS * 2 + m * 16),
                 (const void*)(src + (size_t)n * RS + m * 8));
        }
        if (tid < 128) se_s[(t & 1) * 128 + tid] = g_se[t * 128 + tid];
    };

    issueB(0);
    CP_COMMIT();

    for (int t = 0; t < 16; t++) {
        if (t < 15) { issueB(t + 1); CP_COMMIT(); CP_WAIT1(); }
        else        { CP_WAIT0(); }
        __syncthreads();                            // tile t data visible

        const uint32_t bbuf = sbase + SB + (t & 1) * (BUFE * 2) + b_lane_off;
        float acc[2][4][4];
#pragma unroll
        for (int mf = 0; mf < 2; mf++)
#pragma unroll
            for (int nf = 0; nf < 4; nf++)
#pragma unroll
                for (int i = 0; i < 4; i++) acc[mf][nf][i] = 0.f;

#pragma unroll
        for (int ks = 0; ks < 16; ks++) {
            const uint32_t kb = (uint32_t)(ks * 32);
            uint32_t a[2][4], b[4][2];
#pragma unroll
            for (int mf = 0; mf < 2; mf++)
                ldm4(a[mf], a_base + (uint32_t)(16 * mf * RS * 2) + kb);
            {
                uint32_t bv[4];
                ldm4(bv, bbuf + kb);
                b[0][0] = bv[0]; b[0][1] = bv[1];
                b[1][0] = bv[2]; b[1][1] = bv[3];
                ldm4(bv, bbuf + (uint32_t)(16 * RS * 2) + kb);
                b[2][0] = bv[0]; b[2][1] = bv[1];
                b[3][0] = bv[2]; b[3][1] = bv[3];
            }
#pragma unroll
            for (int mf = 0; mf < 2; mf++)
#pragma unroll
                for (int nf = 0; nf < 4; nf++)
                    mma16816(acc[mf][nf], a[mf], b[nf]);
        }

        // ---- rowmin fold + fp16 tt dump
        const float* sep = se_s + (t & 1) * 128;
        float rmin[2][2];
#pragma unroll
        for (int mf = 0; mf < 2; mf++) { rmin[mf][0] = 1e30f; rmin[mf][1] = 1e30f; }

#pragma unroll
        for (int mf = 0; mf < 2; mf++) {
            const int r0 = n0 + 32 * WM + 16 * mf + qr;
#pragma unroll
            for (int nf = 0; nf < 4; nf++) {
                const int cb = 32 * WN + 8 * nf + 2 * qc;
                const float s0 = sep[cb], s1 = sep[cb + 1];
                const size_t col = (size_t)(t * 128 + cb);
                float2 v;
                v.x = fmaf(-2.f, acc[mf][nf][0], s0);
                v.y = fmaf(-2.f, acc[mf][nf][1], s1);
                rmin[mf][0] = fminf(rmin[mf][0], fminf(v.x, v.y));
                *(__half2*)(g_tth + ((size_t)r0 << 11) + col) = __float22half2_rn(v);
                v.x = fmaf(-2.f, acc[mf][nf][2], s0);
                v.y = fmaf(-2.f, acc[mf][nf][3], s1);
                rmin[mf][1] = fminf(rmin[mf][1], fminf(v.x, v.y));
                *(__half2*)(g_tth + ((size_t)(r0 + 8) << 11) + col) = __float22half2_rn(v);
            }
        }
#pragma unroll
        for (int mf = 0; mf < 2; mf++)
#pragma unroll
            for (int h = 0; h < 2; h++) {
                float v = rmin[mf][h];
                v = fminf(v, __shfl_xor_sync(0xffffffffu, v, 1));
                v = fminf(v, __shfl_xor_sync(0xffffffffu, v, 2));
                if (qc == 0) {                      // exclusive (row, WN) owner
                    int r = 32 * WM + 16 * mf + qr + 8 * h;
                    float* p = &rowm[r * 4 + WN];
                    *p = fminf(*p, v);
                }
            }
        __syncthreads();    // B buf reads + rowm updates done before next tile
    }

    if (tid < 128) {
        const float* rp = rowm + tid * 4;
        g_min[n0 + tid] = fminf(fminf(rp[0], rp[1]), fminf(rp[2], rp[3]));
    }
}

// ===========================================================================
// Streaming scan + exact rescore. One warp per row. thr comes from g_min
// (filter-computed fp32 row min) -> single pass: load 16B (8 cols), compare,
// mask; then bit-exact R1 rescore per hit, lexicographic (d,k) reduce.
// ===========================================================================
__global__ __launch_bounds__(256) void k_scan(const float* __restrict__ z,
                                              const float* __restrict__ emb) {
    __shared__ float zrow[8][256];
    const int tid = threadIdx.x, w = tid >> 5, lane = tid & 31;
    const int n0 = blockIdx.x * 8;
    const int bb = n0 >> 12;
    const float* zb = z + (size_t)bb * 1048576 + (n0 & 4095);
    {
        int r = tid & 7, cp = tid >> 3;
#pragma unroll
        for (int jj = 0; jj < 8; jj++) {
            int c = cp + jj * 32;
            zrow[r][c] = zb[(size_t)c * 4096 + r];
        }
    }
    __syncthreads();

    const int n = n0 + w;
    const float sz = g_sz[n];
    const float thr = g_min[n] + FILT_EPS;
    const float* zr = zrow[w];
    // lane covers cols 256*j + 8*lane + {0..7}, j = 0..7 (16B loads)
    const uint4* tp = (const uint4*)(g_tth + ((size_t)n << 11)) + lane;

    unsigned long long mask = 0ull;
#pragma unroll
    for (int j = 0; j < 8; j++) {
        uint4 v = tp[32 * j];
        float2 f0 = __half22float2(*(__half2*)&v.x);
        float2 f1 = __half22float2(*(__half2*)&v.y);
        float2 f2 = __half22float2(*(__half2*)&v.z);
        float2 f3 = __half22float2(*(__half2*)&v.w);
        unsigned b = 0;
        b |= (f0.x <= thr) ? 1u : 0u;
        b |= (f0.y <= thr) ? 2u : 0u;
        b |= (f1.x <= thr) ? 4u : 0u;
        b |= (f1.y <= thr) ? 8u : 0u;
        b |= (f2.x <= thr) ? 16u : 0u;
        b |= (f2.y <= thr) ? 32u : 0u;
        b |= (f3.x <= thr) ? 64u : 0u;
        b |= (f3.y <= thr) ? 128u : 0u;
        mask |= ((unsigned long long)b) << (8 * j);
    }

    float bd = 1e38f;
    int bi = 0x7fffffff;
    while (mask) {
        int b = __ffsll((long long)mask) - 1;       // b = 8*j + s
        mask &= mask - 1;
        int k = 256 * (b >> 3) + 8 * lane + (b & 7);
        const float* e = emb + (size_t)k * 256;
        float acc = 0.f;
#pragma unroll 8
        for (int c = 0; c < 256; c++) acc = fmaf(zr[c], e[c], acc);
        float d = (sz + g_se[k]) - 2.0f * acc;
        if (d < bd || (d == bd && k < bi)) { bd = d; bi = k; }
    }
#pragma unroll
    for (int off = 16; off > 0; off >>= 1) {
        float d2 = __shfl_down_sync(0xffffffffu, bd, off);
        int i2 = __shfl_down_sync(0xffffffffu, bi, off);
        if (d2 < bd || (d2 == bd && i2 < bi)) { bd = d2; bi = i2; }
    }
    if (lane == 0) g_idx[n] = bi;
}

// ===========================================================================
// gather + z_q_st + loss partials (2 rows per warp)
// ===========================================================================
__global__ __launch_bounds__(256) void k_gather(const float* __restrict__ z,
                                                const float* __restrict__ emb,
                                                float* __restrict__ out) {
    const int tid = threadIdx.x, lane = tid & 31, w = tid >> 5;
    const int n = blockIdx.x * 16 + w * 2;
    const int iA = g_idx[n], iB = g_idx[n + 1];
    const size_t eoA = (size_t)iA * 256 + lane * 8;
    const size_t eoB = (size_t)iB * 256 + lane * 8;
    const size_t zoA = (size_t)n * 256 + lane * 8;
    const size_t zoB = zoA + 256;

    float4 a0 = *(const float4*)(emb + eoA), a1 = *(const float4*)(emb + eoA + 4);
    float4 b0 = *(const float4*)(emb + eoB), b1 = *(const float4*)(emb + eoB + 4);
    float4 x0 = *(const float4*)(z + zoA),   x1 = *(const float4*)(z + zoA + 4);
    float4 y0 = *(const float4*)(z + zoB),   y1 = *(const float4*)(z + zoB + 4);

    float dA[8] = {a0.x - x0.x, a0.y - x0.y, a0.z - x0.z, a0.w - x0.w,
                   a1.x - x1.x, a1.y - x1.y, a1.z - x1.z, a1.w - x1.w};
    float dB[8] = {b0.x - y0.x, b0.y - y0.y, b0.z - y0.z, b0.w - y0.w,
                   b1.x - y1.x, b1.y - y1.y, b1.z - y1.z, b1.w - y1.w};

    float4 o;
    o.x = x0.x + dA[0]; o.y = x0.y + dA[1]; o.z = x0.z + dA[2]; o.w = x0.w + dA[3];
    *(float4*)(out + zoA) = o;
    o.x = x1.x + dA[4]; o.y = x1.y + dA[5]; o.z = x1.z + dA[6]; o.w = x1.w + dA[7];
    *(float4*)(out + zoA + 4) = o;
    o.x = y0.x + dB[0]; o.y = y0.y + dB[1]; o.z = y0.z + dB[2]; o.w = y0.w + dB[3];
    *(float4*)(out + zoB) = o;
    o.x = y1.x + dB[4]; o.y = y1.y + dB[5]; o.z = y1.z + dB[6]; o.w = y1.w + dB[7];
    *(float4*)(out + zoB + 4) = o;

    double s = 0.0;
#pragma unroll
    for (int i = 0; i < 8; i++) s += (double)dA[i] * dA[i] + (double)dB[i] * dB[i];
#pragma unroll
    for (int off = 16; off > 0; off >>= 1)
        s += __shfl_down_sync(0xffffffffu, s, off);

    __shared__ double sp[8];
    if (lane == 0) sp[w] = s;
    __syncthreads();
    if (tid == 0) {
        double t = 0.0;
#pragma unroll
        for (int i = 0; i < 8; i++) t += sp[i];
        g_part[blockIdx.x] = t;
    }
}

__global__ void k_final(float* __restrict__ out) {
    __shared__ double red[256];
    int tid = threadIdx.x;
    double s = 0.0;
    for (int i = tid; i < NPART; i += 256) s += g_part[i];
    red[tid] = s;
    __syncthreads();
    for (int st = 128; st > 0; st >>= 1) {
        if (tid < st) red[tid] += red[tid + st];
        __syncthreads();
    }
    if (tid == 0) {
        float m = (float)(red[0] / (double)ZQN);
        out[LOSS_OFF] = m + 0.25f * m;
    }
    for (int i = tid; i < NROWS; i += 256) out[IDX_OFF + i] = (float)g_idx[i];
}

// ===========================================================================
extern "C" void kernel_launch(void* const* d_in, const int* in_sizes, int n_in,
                              void* d_out, int out_size) {
    const float* z = (const float*)d_in[0];
    const float* emb = (const float*)d_in[1];
    float* out = (float*)d_out;

    k_se<<<16, 128>>>(emb);
    k_sz<<<128, 256>>>(z);
    k_cvt<<<128, 256>>>(emb);

    cudaFuncSetAttribute(k_filter, cudaFuncAttributeMaxDynamicSharedMemorySize, SMEM_F);
    k_filter<<<256, 512, SMEM_F>>>(z);

    k_scan<<<4096, 256>>>(z, emb);
    k_gather<<<2048, 256>>>(z, emb, out);
    k_final<<<1, 256>>>(out);
}

// round 16
// speedup vs baseline: 1.0340x; 1.0340x over previous
#include <cuda_runtime.h>
#include <cuda_bf16.h>
#include <cuda_fp16.h>
#include <cstdint>

#define NROWS   32768
#define KCODES  2048
#define CDIM    256
#define ZQN     8388608
#define LOSS_OFF 8388608
#define IDX_OFF  8388609
#define NPART   2048
#define FILT_EPS 7.5e-4f

// B tile row stride in bf16 (256 data + 8 pad; 528B = 33*16; conflict-free frags)
#define RS 264

// ---- scratch (device globals; no allocation allowed) ----------------------
__device__ float          g_se[KCODES];
__device__ float          g_sz[NROWS];
__device__ float          g_tmin[(size_t)NROWS * 16];   // per (row, tile) fp32 min
__device__ int            g_idx[NROWS];
__device__ double         g_part[NPART];
__device__ __nv_bfloat16  g_embh[KCODES * RS];          // emb in bf16, padded rows
__device__ __half         g_tth[(size_t)NROWS * KCODES]; // fp16 score dump (128MB)

// ---- helpers ---------------------------------------------------------------
__device__ __forceinline__ uint32_t smem_u32(const void* p) {
    uint32_t a;
    asm("{ .reg .u64 t; cvta.to.shared.u64 t, %1; cvt.u32.u64 %0, t; }"
        : "=r"(a) : "l"(p));
    return a;
}
__device__ __forceinline__ void cp16(uint32_t dst, const void* src) {
    asm volatile("cp.async.cg.shared.global [%0], [%1], 16;"
                 :: "r"(dst), "l"(src) : "memory");
}
#define CP_COMMIT() asm volatile("cp.async.commit_group;" ::: "memory")
#define CP_WAIT1()  asm volatile("cp.async.wait_group 1;" ::: "memory")
#define CP_WAIT0()  asm volatile("cp.async.wait_group 0;" ::: "memory")

// bf16 warp MMA m16n8k16 (Ampere-era PTX; valid on plain sm_103 target)
__device__ __forceinline__ void mma16816(float* d, const uint32_t* a, const uint32_t* b) {
    asm volatile(
        "mma.sync.aligned.m16n8k16.row.col.f32.bf16.bf16.f32 "
        "{%0,%1,%2,%3}, {%4,%5,%6,%7}, {%8,%9}, {%0,%1,%2,%3};"
        : "+f"(d[0]), "+f"(d[1]), "+f"(d[2]), "+f"(d[3])
        : "r"(a[0]), "r"(a[1]), "r"(a[2]), "r"(a[3]), "r"(b[0]), "r"(b[1]));
}
__device__ __forceinline__ void ldm4(uint32_t* r, uint32_t a) {
    asm volatile("ldmatrix.sync.aligned.m8n8.x4.shared.b16 {%0,%1,%2,%3}, [%4];"
        : "=r"(r[0]), "=r"(r[1]), "=r"(r[2]), "=r"(r[3]) : "r"(a));
}

// ---- smem layout for k_filter (bytes) --------------------------------------
#define SA    0                 // A: 128 x RS bf16                    67584
#define SB    67584             // B: 2 x (128 x RS) bf16             135168
#define SSE   202752            // se staging [2][128] f32              1024
#define SRT   203776            // rowt [2][128][4] f32                 4096
#define SMEM_F 207872
#define BUFE  (128 * RS)

// ===========================================================================
// Merged prep: per-code norms (blocks 0-7), per-row norms (8-135),
// emb fp32->bf16 (136-263). All exact fp32, same sequences as R1.
// ===========================================================================
__global__ __launch_bounds__(256) void k_prep(const float* __restrict__ emb,
                                              const float* __restrict__ z) {
    const int bx = blockIdx.x, tid = threadIdx.x;
    if (bx < 8) {
        int k = bx * 256 + tid;
        const float4* e = (const float4*)(emb + (size_t)k * CDIM);
        float s = 0.f;
#pragma unroll 8
        for (int i = 0; i < CDIM / 4; i++) {
            float4 v = e[i];
            s += v.x * v.x; s += v.y * v.y; s += v.z * v.z; s += v.w * v.w;
        }
        g_se[k] = s;
    } else if (bx < 136) {
        int n = (bx - 8) * 256 + tid;
        int b = n >> 12, s = n & 4095;
        const float* p = z + (size_t)b * 1048576 + s;
        float acc = 0.f;
#pragma unroll 8
        for (int c = 0; c < CDIM; c++) {
            float v = p[(size_t)c * 4096];
            acc += v * v;
        }
        g_sz[n] = acc;
    } else {
        int g = (bx - 136) * 256 + tid;
        int code = g >> 4, m = g & 15;
        const float4* src = (const float4*)(emb + (size_t)code * CDIM + m * 16);
        __nv_bfloat162 v[8];
#pragma unroll
        for (int i = 0; i < 4; i++) {
            float4 f = src[i];
            v[2 * i]     = __floats2bfloat162_rn(f.x, f.y);
            v[2 * i + 1] = __floats2bfloat162_rn(f.z, f.w);
        }
        __nv_bfloat162* dst = (__nv_bfloat162*)(g_embh + (size_t)code * RS + m * 16);
#pragma unroll
        for (int i = 0; i < 8; i++) dst[i] = v[i];
    }
}

// ===========================================================================
// Warp-MMA bf16 score kernel, 512 threads, 4x4 warp grid (warp tile 32x32).
// Dumps tt = se - 2*dot as fp16 AND per-(row, tile) fp32 minima (g_tmin).
// rowt double-buffered (t&1) so the fold needs no extra barrier.
// ===========================================================================
__global__ __launch_bounds__(512, 1) void k_filter(const float* __restrict__ z) {
    extern __shared__ char smem[];
    __nv_bfloat16* As   = (__nv_bfloat16*)(smem + SA);
    float*         se_s = (float*)(smem + SSE);
    float*         rowt = (float*)(smem + SRT);      // [2][128][4]
    const uint32_t sbase = smem_u32(smem);

    const int tid = threadIdx.x, lane = tid & 31, wid = tid >> 5;
    const int qr = lane >> 2, qc = lane & 3;
    const int WM = wid & 3, WN = wid >> 2;          // 4 x 4 warp grid
    const int n0 = blockIdx.x * 128;

    // ---- A fill: z rows n0..n0+127 -> bf16 As[row][c]
    {
        const float* zb = z + ((size_t)(n0 >> 12)) * 1048576 + (n0 & 4095);
#pragma unroll 8
        for (int i = 0; i < 64; i++) {
            int u = tid + i * 512;
            int row = u & 127, c = u >> 7;
            As[row * RS + c] = __float2bfloat16(zb[(size_t)c * 4096 + row]);
        }
    }

    // ---- ldmatrix per-lane base addresses ----
    const int l7 = lane & 7;
    const int a_row  = 32 * WM + l7 + 8 * ((lane >> 3) & 1);
    const int a_koff = (lane >> 4) * 8;
    const uint32_t a_base = sbase + SA + (uint32_t)((a_row * RS + a_koff) * 2);
    const int bt = lane >> 3;
    const int b_rowoff = 8 * (bt >> 1) + l7;
    const int b_koff = 8 * (bt & 1);
    const uint32_t b_lane_off = (uint32_t)(((32 * WN + b_rowoff) * RS + b_koff) * 2);

    // ---- B tile async loader ----
    auto issueB = [&](int t) {
        const __nv_bfloat16* src = g_embh + (size_t)t * 128 * RS;
        uint32_t dbase = sbase + SB + (t & 1) * (BUFE * 2);
#pragma unroll
        for (int i = 0; i < 8; i++) {
            int u = tid + i * 512;
            int n = u >> 5, m = u & 31;
            cp16(dbase + (uint32_t)(n * RS * 2 + m * 16),
                 (const void*)(src + (size_t)n * RS + m * 8));
        }
        if (tid < 128) se_s[(t & 1) * 128 + tid] = g_se[t * 128 + tid];
    };

    issueB(0);
    CP_COMMIT();

    for (int t = 0; t < 16; t++) {
        if (t < 15) { issueB(t + 1); CP_COMMIT(); CP_WAIT1(); }
        else        { CP_WAIT0(); }
        __syncthreads();                            // tile t data visible

        const uint32_t bbuf = sbase + SB + (t & 1) * (BUFE * 2) + b_lane_off;
        float acc[2][4][4];
#pragma unroll
        for (int mf = 0; mf < 2; mf++)
#pragma unroll
            for (int nf = 0; nf < 4; nf++)
#pragma unroll
                for (int i = 0; i < 4; i++) acc[mf][nf][i] = 0.f;

#pragma unroll
        for (int ks = 0; ks < 16; ks++) {
            const uint32_t kb = (uint32_t)(ks * 32);
            uint32_t a[2][4], b[4][2];
#pragma unroll
            for (int mf = 0; mf < 2; mf++)
                ldm4(a[mf], a_base + (uint32_t)(16 * mf * RS * 2) + kb);
            {
                uint32_t bv[4];
                ldm4(bv, bbuf + kb);
                b[0][0] = bv[0]; b[0][1] = bv[1];
                b[1][0] = bv[2]; b[1][1] = bv[3];
                ldm4(bv, bbuf + (uint32_t)(16 * RS * 2) + kb);
                b[2][0] = bv[0]; b[2][1] = bv[1];
                b[3][0] = bv[2]; b[3][1] = bv[3];
            }
#pragma unroll
            for (int mf = 0; mf < 2; mf++)
#pragma unroll
                for (int nf = 0; nf < 4; nf++)
                    mma16816(acc[mf][nf], a[mf], b[nf]);
        }

        // ---- per-tile rowmin + fp16 tt dump
        const float* sep = se_s + (t & 1) * 128;
        float rmin[2][2];
#pragma unroll
        for (int mf = 0; mf < 2; mf++) { rmin[mf][0] = 1e30f; rmin[mf][1] = 1e30f; }

#pragma unroll
        for (int mf = 0; mf < 2; mf++) {
            const int r0 = n0 + 32 * WM + 16 * mf + qr;
#pragma unroll
            for (int nf = 0; nf < 4; nf++) {
                const int cb = 32 * WN + 8 * nf + 2 * qc;
                const float s0 = sep[cb], s1 = sep[cb + 1];
                const size_t col = (size_t)(t * 128 + cb);
                float2 v;
                v.x = fmaf(-2.f, acc[mf][nf][0], s0);
                v.y = fmaf(-2.f, acc[mf][nf][1], s1);
                rmin[mf][0] = fminf(rmin[mf][0], fminf(v.x, v.y));
                *(__half2*)(g_tth + ((size_t)r0 << 11) + col) = __float22half2_rn(v);
                v.x = fmaf(-2.f, acc[mf][nf][2], s0);
                v.y = fmaf(-2.f, acc[mf][nf][3], s1);
                rmin[mf][1] = fminf(rmin[mf][1], fminf(v.x, v.y));
                *(__half2*)(g_tth + ((size_t)(r0 + 8) << 11) + col) = __float22half2_rn(v);
            }
        }
        float* rt = rowt + (t & 1) * 512;
#pragma unroll
        for (int mf = 0; mf < 2; mf++)
#pragma unroll
            for (int h = 0; h < 2; h++) {
                float v = rmin[mf][h];
                v = fminf(v, __shfl_xor_sync(0xffffffffu, v, 1));
                v = fminf(v, __shfl_xor_sync(0xffffffffu, v, 2));
                if (qc == 0) {                      // exclusive (row, WN) owner
                    int r = 32 * WM + 16 * mf + qr + 8 * h;
                    rt[r * 4 + WN] = v;             // plain store: once per tile
                }
            }
        __syncthreads();    // B buf reads + rowt writes done

        // fold this tile's rowt -> g_tmin (other buffer used by next tile;
        // this buffer next written at tile t+2, after >=2 barriers)
        if (tid < 128) {
            const float* rp = rt + tid * 4;
            g_tmin[(size_t)(n0 + tid) * 16 + t] =
                fminf(fminf(rp[0], rp[1]), fminf(rp[2], rp[3]));
        }
    }
}

// ===========================================================================
// Sparse scan + exact rescore. One warp per row:
//  - 16 per-tile minima (64B), warp-min -> thr = min + eps
//  - only tiles with tmin <= thr are read (256B each, expected ~1.3/row)
//  - candidates: tt_f16 <= thr; exact fp32 rescore (bit-exact R1 sequence),
//    lexicographic (d,k) reduce. Writes g_idx and out idx-as-float.
// ===========================================================================
__global__ __launch_bounds__(256) void k_scan(const float* __restrict__ z,
                                              const float* __restrict__ emb,
                                              float* __restrict__ out) {
    __shared__ float zrow[8][256];
    const int tid = threadIdx.x, w = tid >> 5, lane = tid & 31;
    const int n0 = blockIdx.x * 8;
    const int bb = n0 >> 12;
    const float* zb = z + (size_t)bb * 1048576 + (n0 & 4095);
    {
        int r = tid & 7, cp = tid >> 3;
#pragma unroll
        for (int jj = 0; jj < 8; jj++) {
            int c = cp + jj * 32;
            zrow[r][c] = zb[(size_t)c * 4096 + r];
        }
    }
    __syncthreads();

    const int n = n0 + w;
    const float sz = g_sz[n];
    const float* zr = zrow[w];

    float m = (lane < 16) ? g_tmin[(size_t)n * 16 + lane] : 1e30f;
    float mn = m;
#pragma unroll
    for (int off = 16; off > 0; off >>= 1)
        mn = fminf(mn, __shfl_xor_sync(0xffffffffu, mn, off));
    const float thr = mn + FILT_EPS;
    unsigned tmask = __ballot_sync(0xffffffffu, (lane < 16) && (m <= thr));

    float bd = 1e38f;
    int bi = 0x7fffffff;
    while (tmask) {                                  // warp-uniform tile loop
        int t = __ffs(tmask) - 1;
        tmask &= tmask - 1;
        uint2 v = *(const uint2*)(g_tth + ((size_t)n << 11) + t * 128 + 4 * lane);
        float2 f0 = __half22float2(*(__half2*)&v.x);
        float2 f1 = __half22float2(*(__half2*)&v.y);
        unsigned hm = 0;
        hm |= (f0.x <= thr) ? 1u : 0u;
        hm |= (f0.y <= thr) ? 2u : 0u;
        hm |= (f1.x <= thr) ? 4u : 0u;
        hm |= (f1.y <= thr) ? 8u : 0u;
        while (hm) {
            int s = __ffs(hm) - 1;
            hm &= hm - 1;
            int k = t * 128 + 4 * lane + s;
            const float* e = emb + (size_t)k * 256;
            float acc = 0.f;
#pragma unroll 8
            for (int c = 0; c < 256; c++) acc = fmaf(zr[c], e[c], acc);
            float d = (sz + g_se[k]) - 2.0f * acc;
            if (d < bd || (d == bd && k < bi)) { bd = d; bi = k; }
        }
    }
#pragma unroll
    for (int off = 16; off > 0; off >>= 1) {
        float d2 = __shfl_down_sync(0xffffffffu, bd, off);
        int i2 = __shfl_down_sync(0xffffffffu, bi, off);
        if (d2 < bd || (d2 == bd && i2 < bi)) { bd = d2; bi = i2; }
    }
    if (lane == 0) {
        g_idx[n] = bi;
        out[IDX_OFF + n] = (float)bi;
    }
}

// ===========================================================================
// gather + z_q_st + loss partials (2 rows per warp)
// ===========================================================================
__global__ __launch_bounds__(256) void k_gather(const float* __restrict__ z,
                                                const float* __restrict__ emb,
                                                float* __restrict__ out) {
    const int tid = threadIdx.x, lane = tid & 31, w = tid >> 5;
    const int n = blockIdx.x * 16 + w * 2;
    const int iA = g_idx[n], iB = g_idx[n + 1];
    const size_t eoA = (size_t)iA * 256 + lane * 8;
    const size_t eoB = (size_t)iB * 256 + lane * 8;
    const size_t zoA = (size_t)n * 256 + lane * 8;
    const size_t zoB = zoA + 256;

    float4 a0 = *(const float4*)(emb + eoA), a1 = *(const float4*)(emb + eoA + 4);
    float4 b0 = *(const float4*)(emb + eoB), b1 = *(const float4*)(emb + eoB + 4);
    float4 x0 = *(const float4*)(z + zoA),   x1 = *(const float4*)(z + zoA + 4);
    float4 y0 = *(const float4*)(z + zoB),   y1 = *(const float4*)(z + zoB + 4);

    float dA[8] = {a0.x - x0.x, a0.y - x0.y, a0.z - x0.z, a0.w - x0.w,
                   a1.x - x1.x, a1.y - x1.y, a1.z - x1.z, a1.w - x1.w};
    float dB[8] = {b0.x - y0.x, b0.y - y0.y, b0.z - y0.z, b0.w - y0.w,
                   b1.x - y1.x, b1.y - y1.y, b1.z - y1.z, b1.w - y1.w};

    float4 o;
    o.x = x0.x + dA[0]; o.y = x0.y + dA[1]; o.z = x0.z + dA[2]; o.w = x0.w + dA[3];
    *(float4*)(out + zoA) = o;
    o.x = x1.x + dA[4]; o.y = x1.y + dA[5]; o.z = x1.z + dA[6]; o.w = x1.w + dA[7];
    *(float4*)(out + zoA + 4) = o;
    o.x = y0.x + dB[0]; o.y = y0.y + dB[1]; o.z = y0.z + dB[2]; o.w = y0.w + dB[3];
    *(float4*)(out + zoB) = o;
    o.x = y1.x + dB[4]; o.y = y1.y + dB[5]; o.z = y1.z + dB[6]; o.w = y1.w + dB[7];
    *(float4*)(out + zoB + 4) = o;

    double s = 0.0;
#pragma unroll
    for (int i = 0; i < 8; i++) s += (double)dA[i] * dA[i] + (double)dB[i] * dB[i];
#pragma unroll
    for (int off = 16; off > 0; off >>= 1)
        s += __shfl_down_sync(0xffffffffu, s, off);

    __shared__ double sp[8];
    if (lane == 0) sp[w] = s;
    __syncthreads();
    if (tid == 0) {
        double t = 0.0;
#pragma unroll
        for (int i = 0; i < 8; i++) t += sp[i];
        g_part[blockIdx.x] = t;
    }
}

__global__ void k_final(float* __restrict__ out) {
    __shared__ double red[256];
    int tid = threadIdx.x;
    double s = 0.0;
    for (int i = tid; i < NPART; i += 256) s += g_part[i];
    red[tid] = s;
    __syncthreads();
    for (int st = 128; st > 0; st >>= 1) {
        if (tid < st) red[tid] += red[tid + st];
        __syncthreads();
    }
    if (tid == 0) {
        float mloss = (float)(red[0] / (double)ZQN);
        out[LOSS_OFF] = mloss + 0.25f * mloss;
    }
}

// ===========================================================================
extern "C" void kernel_launch(void* const* d_in, const int* in_sizes, int n_in,
                              void* d_out, int out_size) {
    const float* z = (const float*)d_in[0];
    const float* emb = (const float*)d_in[1];
    float* out = (float*)d_out;

    k_prep<<<264, 256>>>(emb, z);

    cudaFuncSetAttribute(k_filter, cudaFuncAttributeMaxDynamicSharedMemorySize, SMEM_F);
    k_filter<<<256, 512, SMEM_F>>>(z);

    k_scan<<<4096, 256>>>(z, emb, out);
    k_gather<<<2048, 256>>>(z, emb, out);
    k_final<<<1, 256>>>(out);
}

// round 17
// speedup vs baseline: 1.1758x; 1.1371x over previous
#include <cuda_runtime.h>
#include <cuda_bf16.h>
#include <cuda_fp16.h>
#include <cstdint>

#define NROWS   32768
#define KCODES  2048
#define CDIM    256
#define ZQN     8388608
#define LOSS_OFF 8388608
#define IDX_OFF  8388609
#define NPART   1024
#define FILT_EPS 7.5e-4f

// B tile row stride in bf16 (256 data + 8 pad; 528B = 33*16; conflict-free frags)
#define RS 264

// ---- scratch (device globals; no allocation allowed) ----------------------
__device__ float          g_se[KCODES];
__device__ float          g_sz[NROWS];
__device__ float          g_tmin[(size_t)NROWS * 16];   // per (row, tile) fp32 min
__device__ int            g_idx[NROWS];
__device__ double         g_part[NPART];
__device__ __nv_bfloat16  g_embh[KCODES * RS];          // emb in bf16, padded rows
__device__ __half         g_tth[(size_t)NROWS * KCODES]; // fp16 score dump (128MB)

// ---- helpers ---------------------------------------------------------------
__device__ __forceinline__ uint32_t smem_u32(const void* p) {
    uint32_t a;
    asm("{ .reg .u64 t; cvta.to.shared.u64 t, %1; cvt.u32.u64 %0, t; }"
        : "=r"(a) : "l"(p));
    return a;
}
__device__ __forceinline__ void cp16(uint32_t dst, const void* src) {
    asm volatile("cp.async.cg.shared.global [%0], [%1], 16;"
                 :: "r"(dst), "l"(src) : "memory");
}
#define CP_COMMIT() asm volatile("cp.async.commit_group;" ::: "memory")
#define CP_WAIT1()  asm volatile("cp.async.wait_group 1;" ::: "memory")
#define CP_WAIT0()  asm volatile("cp.async.wait_group 0;" ::: "memory")

// bf16 warp MMA m16n8k16 (Ampere-era PTX; valid on plain sm_103 target)
__device__ __forceinline__ void mma16816(float* d, const uint32_t* a, const uint32_t* b) {
    asm volatile(
        "mma.sync.aligned.m16n8k16.row.col.f32.bf16.bf16.f32 "
        "{%0,%1,%2,%3}, {%4,%5,%6,%7}, {%8,%9}, {%0,%1,%2,%3};"
        : "+f"(d[0]), "+f"(d[1]), "+f"(d[2]), "+f"(d[3])
        : "r"(a[0]), "r"(a[1]), "r"(a[2]), "r"(a[3]), "r"(b[0]), "r"(b[1]));
}
__device__ __forceinline__ void ldm4(uint32_t* r, uint32_t a) {
    asm volatile("ldmatrix.sync.aligned.m8n8.x4.shared.b16 {%0,%1,%2,%3}, [%4];"
        : "=r"(r[0]), "=r"(r[1]), "=r"(r[2]), "=r"(r[3]) : "r"(a));
}

// ---- smem layout for k_filter (bytes) --------------------------------------
#define SA    0                 // A: 128 x RS bf16                    67584
#define SB    67584             // B: 2 x (128 x RS) bf16             135168
#define SSE   202752            // se staging [2][128] f32              1024
#define SRT   203776            // rowt [2][128][4] f32                 4096
#define SMEM_F 207872
#define BUFE  (128 * RS)

// ===========================================================================
// Merged prep: per-code norms (blocks 0-7), per-row norms (8-135),
// emb fp32->bf16 (136-263). All exact fp32, same sequences as R1.
// ===========================================================================
__global__ __launch_bounds__(256) void k_prep(const float* __restrict__ emb,
                                              const float* __restrict__ z) {
    const int bx = blockIdx.x, tid = threadIdx.x;
    if (bx < 8) {
        int k = bx * 256 + tid;
        const float4* e = (const float4*)(emb + (size_t)k * CDIM);
        float s = 0.f;
#pragma unroll 8
        for (int i = 0; i < CDIM / 4; i++) {
            float4 v = e[i];
            s += v.x * v.x; s += v.y * v.y; s += v.z * v.z; s += v.w * v.w;
        }
        g_se[k] = s;
    } else if (bx < 136) {
        int n = (bx - 8) * 256 + tid;
        int b = n >> 12, s = n & 4095;
        const float* p = z + (size_t)b * 1048576 + s;
        float acc = 0.f;
#pragma unroll 8
        for (int c = 0; c < CDIM; c++) {
            float v = p[(size_t)c * 4096];
            acc += v * v;
        }
        g_sz[n] = acc;
    } else {
        int g = (bx - 136) * 256 + tid;
        int code = g >> 4, m = g & 15;
        const float4* src = (const float4*)(emb + (size_t)code * CDIM + m * 16);
        __nv_bfloat162 v[8];
#pragma unroll
        for (int i = 0; i < 4; i++) {
            float4 f = src[i];
            v[2 * i]     = __floats2bfloat162_rn(f.x, f.y);
            v[2 * i + 1] = __floats2bfloat162_rn(f.z, f.w);
        }
        __nv_bfloat162* dst = (__nv_bfloat162*)(g_embh + (size_t)code * RS + m * 16);
#pragma unroll
        for (int i = 0; i < 8; i++) dst[i] = v[i];
    }
}

// ===========================================================================
// Warp-MMA bf16 score kernel, 512 threads, 4x4 warp grid (warp tile 32x32).
// Dumps tt = se - 2*dot as fp16 AND per-(row, tile) fp32 minima (g_tmin).
// ===========================================================================
__global__ __launch_bounds__(512, 1) void k_filter(const float* __restrict__ z) {
    extern __shared__ char smem[];
    __nv_bfloat16* As   = (__nv_bfloat16*)(smem + SA);
    float*         se_s = (float*)(smem + SSE);
    float*         rowt = (float*)(smem + SRT);      // [2][128][4]
    const uint32_t sbase = smem_u32(smem);

    const int tid = threadIdx.x, lane = tid & 31, wid = tid >> 5;
    const int qr = lane >> 2, qc = lane & 3;
    const int WM = wid & 3, WN = wid >> 2;          // 4 x 4 warp grid
    const int n0 = blockIdx.x * 128;

    // ---- A fill: z rows n0..n0+127 -> bf16 As[row][c]
    {
        const float* zb = z + ((size_t)(n0 >> 12)) * 1048576 + (n0 & 4095);
#pragma unroll 8
        for (int i = 0; i < 64; i++) {
            int u = tid + i * 512;
            int row = u & 127, c = u >> 7;
            As[row * RS + c] = __float2bfloat16(zb[(size_t)c * 4096 + row]);
        }
    }

    // ---- ldmatrix per-lane base addresses ----
    const int l7 = lane & 7;
    const int a_row  = 32 * WM + l7 + 8 * ((lane >> 3) & 1);
    const int a_koff = (lane >> 4) * 8;
    const uint32_t a_base = sbase + SA + (uint32_t)((a_row * RS + a_koff) * 2);
    const int bt = lane >> 3;
    const int b_rowoff = 8 * (bt >> 1) + l7;
    const int b_koff = 8 * (bt & 1);
    const uint32_t b_lane_off = (uint32_t)(((32 * WN + b_rowoff) * RS + b_koff) * 2);

    // ---- B tile async loader ----
    auto issueB = [&](int t) {
        const __nv_bfloat16* src = g_embh + (size_t)t * 128 * RS;
        uint32_t dbase = sbase + SB + (t & 1) * (BUFE * 2);
#pragma unroll
        for (int i = 0; i < 8; i++) {
            int u = tid + i * 512;
            int n = u >> 5, m = u & 31;
            cp16(dbase + (uint32_t)(n * RS * 2 + m * 16),
                 (const void*)(src + (size_t)n * RS + m * 8));
        }
        if (tid < 128) se_s[(t & 1) * 128 + tid] = g_se[t * 128 + tid];
    };

    issueB(0);
    CP_COMMIT();

    for (int t = 0; t < 16; t++) {
        if (t < 15) { issueB(t + 1); CP_COMMIT(); CP_WAIT1(); }
        else        { CP_WAIT0(); }
        __syncthreads();                            // tile t data visible

        const uint32_t bbuf = sbase + SB + (t & 1) * (BUFE * 2) + b_lane_off;
        float acc[2][4][4];
#pragma unroll
        for (int mf = 0; mf < 2; mf++)
#pragma unroll
            for (int nf = 0; nf < 4; nf++)
#pragma unroll
                for (int i = 0; i < 4; i++) acc[mf][nf][i] = 0.f;

#pragma unroll
        for (int ks = 0; ks < 16; ks++) {
            const uint32_t kb = (uint32_t)(ks * 32);
            uint32_t a[2][4], b[4][2];
#pragma unroll
            for (int mf = 0; mf < 2; mf++)
                ldm4(a[mf], a_base + (uint32_t)(16 * mf * RS * 2) + kb);
            {
                uint32_t bv[4];
                ldm4(bv, bbuf + kb);
                b[0][0] = bv[0]; b[0][1] = bv[1];
                b[1][0] = bv[2]; b[1][1] = bv[3];
                ldm4(bv, bbuf + (uint32_t)(16 * RS * 2) + kb);
                b[2][0] = bv[0]; b[2][1] = bv[1];
                b[3][0] = bv[2]; b[3][1] = bv[3];
            }
#pragma unroll
            for (int mf = 0; mf < 2; mf++)
#pragma unroll
                for (int nf = 0; nf < 4; nf++)
                    mma16816(acc[mf][nf], a[mf], b[nf]);
        }

        // ---- per-tile rowmin + fp16 tt dump
        const float* sep = se_s + (t & 1) * 128;
        float rmin[2][2];
#pragma unroll
        for (int mf = 0; mf < 2; mf++) { rmin[mf][0] = 1e30f; rmin[mf][1] = 1e30f; }

#pragma unroll
        for (int mf = 0; mf < 2; mf++) {
            const int r0 = n0 + 32 * WM + 16 * mf + qr;
#pragma unroll
            for (int nf = 0; nf < 4; nf++) {
                const int cb = 32 * WN + 8 * nf + 2 * qc;
                const float s0 = sep[cb], s1 = sep[cb + 1];
                const size_t col = (size_t)(t * 128 + cb);
                float2 v;
                v.x = fmaf(-2.f, acc[mf][nf][0], s0);
                v.y = fmaf(-2.f, acc[mf][nf][1], s1);
                rmin[mf][0] = fminf(rmin[mf][0], fminf(v.x, v.y));
                *(__half2*)(g_tth + ((size_t)r0 << 11) + col) = __float22half2_rn(v);
                v.x = fmaf(-2.f, acc[mf][nf][2], s0);
                v.y = fmaf(-2.f, acc[mf][nf][3], s1);
                rmin[mf][1] = fminf(rmin[mf][1], fminf(v.x, v.y));
                *(__half2*)(g_tth + ((size_t)(r0 + 8) << 11) + col) = __float22half2_rn(v);
            }
        }
        float* rt = rowt + (t & 1) * 512;
#pragma unroll
        for (int mf = 0; mf < 2; mf++)
#pragma unroll
            for (int h = 0; h < 2; h++) {
                float v = rmin[mf][h];
                v = fminf(v, __shfl_xor_sync(0xffffffffu, v, 1));
                v = fminf(v, __shfl_xor_sync(0xffffffffu, v, 2));
                if (qc == 0) {                      // exclusive (row, WN) owner
                    int r = 32 * WM + 16 * mf + qr + 8 * h;
                    rt[r * 4 + WN] = v;
                }
            }
        __syncthreads();    // B buf reads + rowt writes done

        if (tid < 128) {
            const float* rp = rt + tid * 4;
            g_tmin[(size_t)(n0 + tid) * 16 + t] =
                fminf(fminf(rp[0], rp[1]), fminf(rp[2], rp[3]));
        }
    }
}

// ===========================================================================
// Sparse scan + exact rescore (unchanged from R16).
// ===========================================================================
__global__ __launch_bounds__(256) void k_scan(const float* __restrict__ z,
                                              const float* __restrict__ emb,
                                              float* __restrict__ out) {
    __shared__ float zrow[8][256];
    const int tid = threadIdx.x, w = tid >> 5, lane = tid & 31;
    const int n0 = blockIdx.x * 8;
    const int bb = n0 >> 12;
    const float* zb = z + (size_t)bb * 1048576 + (n0 & 4095);
    {
        int r = tid & 7, cp = tid >> 3;
#pragma unroll
        for (int jj = 0; jj < 8; jj++) {
            int c = cp + jj * 32;
            zrow[r][c] = zb[(size_t)c * 4096 + r];
        }
    }
    __syncthreads();

    const int n = n0 + w;
    const float sz = g_sz[n];
    const float* zr = zrow[w];

    float m = (lane < 16) ? g_tmin[(size_t)n * 16 + lane] : 1e30f;
    float mn = m;
#pragma unroll
    for (int off = 16; off > 0; off >>= 1)
        mn = fminf(mn, __shfl_xor_sync(0xffffffffu, mn, off));
    const float thr = mn + FILT_EPS;
    unsigned tmask = __ballot_sync(0xffffffffu, (lane < 16) && (m <= thr));

    float bd = 1e38f;
    int bi = 0x7fffffff;
    while (tmask) {
        int t = __ffs(tmask) - 1;
        tmask &= tmask - 1;
        uint2 v = *(const uint2*)(g_tth + ((size_t)n << 11) + t * 128 + 4 * lane);
        float2 f0 = __half22float2(*(__half2*)&v.x);
        float2 f1 = __half22float2(*(__half2*)&v.y);
        unsigned hm = 0;
        hm |= (f0.x <= thr) ? 1u : 0u;
        hm |= (f0.y <= thr) ? 2u : 0u;
        hm |= (f1.x <= thr) ? 4u : 0u;
        hm |= (f1.y <= thr) ? 8u : 0u;
        while (hm) {
            int s = __ffs(hm) - 1;
            hm &= hm - 1;
            int k = t * 128 + 4 * lane + s;
            const float* e = emb + (size_t)k * 256;
            float acc = 0.f;
#pragma unroll 8
            for (int c = 0; c < 256; c++) acc = fmaf(zr[c], e[c], acc);
            float d = (sz + g_se[k]) - 2.0f * acc;
            if (d < bd || (d == bd && k < bi)) { bd = d; bi = k; }
        }
    }
#pragma unroll
    for (int off = 16; off > 0; off >>= 1) {
        float d2 = __shfl_down_sync(0xffffffffu, bd, off);
        int i2 = __shfl_down_sync(0xffffffffu, bi, off);
        if (d2 < bd || (d2 == bd && i2 < bi)) { bd = d2; bi = i2; }
    }
    if (lane == 0) {
        g_idx[n] = bi;
        out[IDX_OFF + n] = (float)bi;
    }
}

// ===========================================================================
// gather + z_q_st + loss partials: 4 rows per warp (deep MLP), fp32 loss
// accumulation in the hot path (double only for block partials).
// ===========================================================================
__global__ __launch_bounds__(256) void k_gather(const float* __restrict__ z,
                                                const float* __restrict__ emb,
                                                float* __restrict__ out) {
    const int tid = threadIdx.x, lane = tid & 31, w = tid >> 5;
    const int n = blockIdx.x * 32 + w * 4;

    int id[4];
#pragma unroll
    for (int r = 0; r < 4; r++) id[r] = g_idx[n + r];

    float4 e0[4], e1[4], z0[4], z1[4];
#pragma unroll
    for (int r = 0; r < 4; r++) {
        const size_t eo = (size_t)id[r] * 256 + lane * 8;
        const size_t zo = (size_t)(n + r) * 256 + lane * 8;
        e0[r] = *(const float4*)(emb + eo);
        e1[r] = *(const float4*)(emb + eo + 4);
        z0[r] = *(const float4*)(z + zo);
        z1[r] = *(const float4*)(z + zo + 4);
    }

    float ls = 0.f;
#pragma unroll
    for (int r = 0; r < 4; r++) {
        const size_t zo = (size_t)(n + r) * 256 + lane * 8;
        float d0 = e0[r].x - z0[r].x, d1 = e0[r].y - z0[r].y;
        float d2 = e0[r].z - z0[r].z, d3 = e0[r].w - z0[r].w;
        float d4 = e1[r].x - z1[r].x, d5 = e1[r].y - z1[r].y;
        float d6 = e1[r].z - z1[r].z, d7 = e1[r].w - z1[r].w;
        float4 o;
        o.x = z0[r].x + d0; o.y = z0[r].y + d1; o.z = z0[r].z + d2; o.w = z0[r].w + d3;
        *(float4*)(out + zo) = o;
        o.x = z1[r].x + d4; o.y = z1[r].y + d5; o.z = z1[r].z + d6; o.w = z1[r].w + d7;
        *(float4*)(out + zo + 4) = o;
        ls += d0 * d0 + d1 * d1 + d2 * d2 + d3 * d3;
        ls += d4 * d4 + d5 * d5 + d6 * d6 + d7 * d7;
    }

#pragma unroll
    for (int off = 16; off > 0; off >>= 1)
        ls += __shfl_down_sync(0xffffffffu, ls, off);

    __shared__ double sp[8];
    if (lane == 0) sp[w] = (double)ls;
    __syncthreads();
    if (tid == 0) {
        double t = 0.0;
#pragma unroll
        for (int i = 0; i < 8; i++) t += sp[i];
        g_part[blockIdx.x] = t;
    }
}

__global__ void k_final(float* __restrict__ out) {
    __shared__ double red[256];
    int tid = threadIdx.x;
    double s = 0.0;
    for (int i = tid; i < NPART; i += 256) s += g_part[i];
    red[tid] = s;
    __syncthreads();
    for (int st = 128; st > 0; st >>= 1) {
        if (tid < st) red[tid] += red[tid + st];
        __syncthreads();
    }
    if (tid == 0) {
        float mloss = (float)(red[0] / (double)ZQN);
        out[LOSS_OFF] = mloss + 0.25f * mloss;
    }
}

// ===========================================================================
extern "C" void kernel_launch(void* const* d_in, const int* in_sizes, int n_in,
                              void* d_out, int out_size) {
    const float* z = (const float*)d_in[0];
    const float* emb = (const float*)d_in[1];
    float* out = (float*)d_out;

    k_prep<<<264, 256>>>(emb, z);

    cudaFuncSetAttribute(k_filter, cudaFuncAttributeMaxDynamicSharedMemorySize, SMEM_F);
    k_filter<<<256, 512, SMEM_F>>>(z);

    k_scan<<<4096, 256>>>(z, emb, out);
    k_gather<<<1024, 256>>>(z, emb, out);
    k_final<<<1, 256>>>(out);
}